// round 7
// baseline (speedup 1.0000x reference)
#include <cuda_runtime.h>
#include <cstdint>

#define BB 16
#define NN 1024
#define DD 64
#define NHH 4
#define HDD 16
#define HH 256
#define WW 256

#define NSTRIPE 16            // y-stripes per batch (16 rows each)
#define BINCAP 256            // points per bin capacity (mean 64, >20 sigma)
#define CHCHUNK 8             // channels staged per gather block
#define ROWW 260              // smem row stride (words), float4-aligned
#define CHSTR (20*ROWW + 4)   // 5204: channel stride, banks 20c mod 32 distinct

// ---------------- scratch (device globals: no runtime allocation) ----------
__device__ float g_Q[BB*NHH*NN*HDD];          // (b,h,n,j) 4MB
__device__ float g_K[BB*NHH*NN*HDD];          // 4MB
__device__ float g_V[BB*NHH*NN*HDD];          // 4MB
__device__ float g_PF[BB*NN*DD];              // patch means 4MB
__device__ float g_att[BB*NN*DD];             // pose-scaled attention out 4MB
__device__ float g_pose[BB*DD];               // 1 + pose_mod
__device__ int   g_cnt[BB*NSTRIPE];           // bin counts
__device__ int   g_list[BB*NSTRIPE*BINCAP];   // bin point lists

// ---------------- helpers ---------------------------------------------------
__device__ __forceinline__ float ex2f(float x) {
    float y;
    asm("ex2.approx.f32 %0, %1;" : "=f"(y) : "f"(x));
    return y;
}
__device__ __forceinline__ uint32_t tf32cvt(float f) {
    uint32_t u;
    asm("cvt.rna.tf32.f32 %0, %1;" : "=r"(u) : "f"(f));
    return u;
}
__device__ __forceinline__ void mma_tf32(float& d0, float& d1, float& d2, float& d3,
                                         uint32_t a0, uint32_t a1, uint32_t a2, uint32_t a3,
                                         uint32_t b0, uint32_t b1) {
    asm("mma.sync.aligned.m16n8k8.row.col.f32.tf32.tf32.f32 "
        "{%0,%1,%2,%3}, {%4,%5,%6,%7}, {%8,%9}, {%0,%1,%2,%3};"
        : "+f"(d0), "+f"(d1), "+f"(d2), "+f"(d3)
        : "r"(a0), "r"(a1), "r"(a2), "r"(a3), "r"(b0), "r"(b1));
}

// ---------------- K0: pose scale + zero bin counts --------------------------
__global__ void zero_pose_kernel(const float* __restrict__ pe,
                                 const float* __restrict__ Wp,
                                 const float* __restrict__ bp) {
    if (blockIdx.x == BB) {                 // zero bin counts
        int i = threadIdx.x;                // 64 threads, 256 counts
        #pragma unroll
        for (int j = 0; j < 4; j++) g_cnt[i + 64*j] = 0;
        return;
    }
    int b = blockIdx.x, d = threadIdx.x;
    float s = bp[d];
    #pragma unroll 8
    for (int p = 0; p < 64; p++) s += pe[b*64 + p] * Wp[p*64 + d];
    g_pose[b*64 + d] = 1.0f + s;
}

// ---------------- K0b: bin points by (batch, y-stripe) ----------------------
__global__ __launch_bounds__(256) void bin_kernel(const int* __restrict__ coords) {
    int gp = blockIdx.x*256 + threadIdx.x;
    int b = gp >> 10;
    int y = __ldg(coords + 2*gp);
    int bin = b*NSTRIPE + (y >> 4);
    int slot = atomicAdd(&g_cnt[bin], 1);
    if (slot < BINCAP) g_list[bin*BINCAP + slot] = gp;
}

// ---------------- K1: stripe-binned patch-mean gather -----------------------
// Block = (channel-chunk cc, stripe st, batch b). Streams 20 rows x 8 planes
// into smem (coalesced), then computes patch sums for the stripe's points
// from smem (warp = point, lanes = 8ch x 4col, conflict-free banks).
extern __shared__ float S[];
__global__ __launch_bounds__(256) void stripe_gather_kernel(
    const float* __restrict__ feat, const int* __restrict__ coords)
{
    int t = threadIdx.x;
    int cc = blockIdx.x, st = blockIdx.y, b = blockIdx.z;
    int y0 = st*16;

    // ---- stage 20 rows x 8 channels (zeros outside the map: y zero-pad) ----
    #pragma unroll
    for (int it = 0; it < 40; it++) {
        int i = t + it*256;                  // 0 .. 10239
        int c = i >> 10;                     // /1280? no: 20*64=1280 → use div
        c = i / 1280;
        int rem = i - c*1280;
        int r = rem >> 6;
        int q = rem & 63;
        int yy = y0 - 2 + r;
        float4 v = make_float4(0.f, 0.f, 0.f, 0.f);
        if (yy >= 0 && yy < HH)
            v = __ldg((const float4*)(feat + ((size_t)(b*64 + cc*CHCHUNK + c) << 16)
                                      + yy*WW + q*4));
        *(float4*)&S[c*CHSTR + r*ROWW + q*4] = v;
    }
    __syncthreads();

    // ---- compute patch means for this stripe's points ----
    int w = t >> 5, lane = t & 31;
    int c8 = lane >> 2, k = lane & 3;        // channel sub, col group
    int bin = b*NSTRIPE + st;
    int cnt = min(g_cnt[bin], BINCAP);
    const int* lst = g_list + bin*BINCAP;

    for (int pi = w; pi < cnt; pi += 8) {
        int gp = lst[pi];
        int y = __ldg(coords + 2*gp);        // warp-uniform broadcast
        int x = __ldg(coords + 2*gp + 1);
        int lr = y - y0;                     // staged row of dy=0 (rows lr..lr+4)
        const float* base = S + c8*CHSTR + lr*ROWW;
        float s = 0.f;
        #pragma unroll
        for (int col = k; col < 5; col += 4) {   // k: col k (+ col 4 for k=0)
            int xx = x - 2 + col;
            if (xx >= 0 && xx < WW) {
                const float* p = base + xx;
                s += p[0] + p[ROWW] + p[2*ROWW] + p[3*ROWW] + p[4*ROWW];
            }
        }
        s += __shfl_xor_sync(0xffffffffu, s, 1);
        s += __shfl_xor_sync(0xffffffffu, s, 2);
        if (k == 0)
            g_PF[(size_t)gp*64 + cc*CHCHUNK + c8] = s * 0.04f;
    }
}

// ---------------- K2: Q/K/V projection --------------------------------------
__global__ __launch_bounds__(256) void projection_kernel(
    const float* __restrict__ desc,
    const float* __restrict__ Wq, const float* __restrict__ bq,
    const float* __restrict__ Wk, const float* __restrict__ bk,
    const float* __restrict__ Wv, const float* __restrict__ bv)
{
    __shared__ float pf[32*64];
    __shared__ float dsc[32*64];

    int t = threadIdx.x;
    int gp0 = blockIdx.x * 32;
    int b   = gp0 >> 10;
    int n0  = gp0 & 1023;

    const float4* dsrc = (const float4*)(desc + (size_t)gp0*64);
    const float4* psrc = (const float4*)(g_PF + (size_t)gp0*64);
    ((float4*)dsc)[t]       = dsrc[t];
    ((float4*)dsc)[t + 256] = dsrc[t + 256];
    ((float4*)pf)[t]        = psrc[t];
    ((float4*)pf)[t + 256]  = psrc[t + 256];
    __syncthreads();

    int c = t & 63;
    int pbase = t >> 6;
    float accq[8], acck[8], accv[8];
    float bqc = bq[c], bkc = bk[c], bvc = bv[c];
    #pragma unroll
    for (int i = 0; i < 8; i++) { accq[i]=bqc; acck[i]=bkc; accv[i]=bvc; }
    for (int k = 0; k < 64; k++) {
        float wq = __ldg(Wq + k*64 + c);
        float wk = __ldg(Wk + k*64 + c);
        float wv = __ldg(Wv + k*64 + c);
        #pragma unroll
        for (int i = 0; i < 8; i++) {
            int p = pbase + 4*i;
            float dv = dsc[p*64 + k];
            float pv = pf[p*64 + k];
            accq[i] += dv * wq;
            acck[i] += pv * wk;
            accv[i] += pv * wv;
        }
    }
    int h = c >> 4, j = c & 15;
    size_t base = (size_t)(b*NHH + h) * NN;
    #pragma unroll
    for (int i = 0; i < 8; i++) {
        int p = pbase + 4*i;
        size_t idx = (base + n0 + p) * HDD + j;
        g_Q[idx] = accq[i];
        g_K[idx] = acck[i];
        g_V[idx] = accv[i];
    }
}

// ---------------- K3: all-tf32 tensor-core attention ------------------------
#define KPAD 20
#define VPAD 24
__global__ __launch_bounds__(256) void attn_mma_kernel() {
    __shared__ uint32_t Ks[64*KPAD];     // tf32 bits, [key][d] padded
    __shared__ uint32_t Vs[64*VPAD];     // tf32 bits, [perm key][d] padded

    int t = threadIdx.x;
    int w = t >> 5, lane = t & 31, g = lane >> 2, t4 = lane & 3;
    int b = blockIdx.z, h = blockIdx.y;
    size_t bh = (size_t)(b*NHH + h) * NN * HDD;
    const float* Kg = g_K + bh;
    const float* Vg = g_V + bh;

    int qrow = blockIdx.x*128 + w*16;
    const float* Qp = g_Q + bh + (size_t)qrow*HDD;
    const float CSC = 0.25f * 1.4426950408889634f;

    uint32_t qa[2][4];
    #pragma unroll
    for (int c = 0; c < 2; c++) {
        qa[c][0] = tf32cvt(Qp[ g   *16 + c*8 + t4    ] * CSC);
        qa[c][1] = tf32cvt(Qp[(g+8)*16 + c*8 + t4    ] * CSC);
        qa[c][2] = tf32cvt(Qp[ g   *16 + c*8 + t4 + 4] * CSC);
        qa[c][3] = tf32cvt(Qp[(g+8)*16 + c*8 + t4 + 4] * CSC);
    }

    float o0[4] = {0,0,0,0};
    float o1[4] = {0,0,0,0};
    float rs0 = 0.0f, rs1 = 0.0f;

    int key = t >> 2, dc = t & 3;
    int vrow = (key & ~7) + 4*(key & 1) + ((key & 7) >> 1);

    float4 kreg = ((const float4*)Kg)[t];
    float4 vreg = ((const float4*)Vg)[t];

    for (int tile = 0; tile < 16; tile++) {
        __syncthreads();
        {
            uint32_t* kd = Ks + key*KPAD + dc*4;
            kd[0] = tf32cvt(kreg.x); kd[1] = tf32cvt(kreg.y);
            kd[2] = tf32cvt(kreg.z); kd[3] = tf32cvt(kreg.w);
            uint4 vv;
            vv.x = tf32cvt(vreg.x); vv.y = tf32cvt(vreg.y);
            vv.z = tf32cvt(vreg.z); vv.w = tf32cvt(vreg.w);
            *(uint4*)(Vs + vrow*VPAD + dc*4) = vv;
        }
        __syncthreads();
        if (tile < 15) {
            kreg = ((const float4*)(Kg + (size_t)(tile+1)*64*16))[t];
            vreg = ((const float4*)(Vg + (size_t)(tile+1)*64*16))[t];
        }

        #pragma unroll
        for (int j = 0; j < 8; j++) {
            float d0=0.f, d1=0.f, d2=0.f, d3=0.f;
            #pragma unroll
            for (int c = 0; c < 2; c++) {
                const uint32_t* kb = Ks + (j*8+g)*KPAD + c*8 + t4;
                mma_tf32(d0,d1,d2,d3, qa[c][0],qa[c][1],qa[c][2],qa[c][3],
                         kb[0], kb[4]);
            }
            float p0 = ex2f(d0), p1 = ex2f(d1), p2 = ex2f(d2), p3 = ex2f(d3);
            rs0 += p0 + p1;
            rs1 += p2 + p3;
            uint32_t a0 = tf32cvt(p0), a1 = tf32cvt(p2);
            uint32_t a2 = tf32cvt(p1), a3 = tf32cvt(p3);
            uint32_t b00 = Vs[(j*8 + t4    )*VPAD + g    ];
            uint32_t b01 = Vs[(j*8 + t4 + 4)*VPAD + g    ];
            uint32_t b10 = Vs[(j*8 + t4    )*VPAD + g + 8];
            uint32_t b11 = Vs[(j*8 + t4 + 4)*VPAD + g + 8];
            mma_tf32(o0[0],o0[1],o0[2],o0[3], a0,a1,a2,a3, b00,b01);
            mma_tf32(o1[0],o1[1],o1[2],o1[3], a0,a1,a2,a3, b10,b11);
        }
    }

    rs0 += __shfl_xor_sync(0xffffffff, rs0, 1);
    rs0 += __shfl_xor_sync(0xffffffff, rs0, 2);
    rs1 += __shfl_xor_sync(0xffffffff, rs1, 1);
    rs1 += __shfl_xor_sync(0xffffffff, rs1, 2);
    float inv0 = 1.0f / rs0;
    float inv1 = 1.0f / rs1;

    const float* ps = g_pose + b*64 + h*16;
    size_t r0 = ((size_t)b*NN + qrow + g    )*64 + h*16;
    size_t r1 = ((size_t)b*NN + qrow + g + 8)*64 + h*16;
    #pragma unroll
    for (int nd = 0; nd < 2; nd++) {
        const float* o = nd ? o1 : o0;
        int cc = nd*8 + 2*t4;
        float p0 = ps[cc], p1 = ps[cc+1];
        *(float2*)&g_att[r0 + cc] = make_float2(o[0]*inv0*p0, o[1]*inv0*p1);
        *(float2*)&g_att[r1 + cc] = make_float2(o[2]*inv1*p0, o[3]*inv1*p1);
    }
}

// ---------------- K4: out = g_att @ Wo + bo (32 rows/block) -----------------
__global__ __launch_bounds__(128) void outproj_kernel(const float* __restrict__ Wo,
                                                      const float* __restrict__ bo,
                                                      float* __restrict__ out) {
    __shared__ float fat[32*64];
    int t = threadIdx.x;
    size_t rbase = (size_t)blockIdx.x * 32;
    const float4* src = (const float4*)(g_att + rbase*64);
    float4* dst = (float4*)fat;
    #pragma unroll
    for (int i = 0; i < 4; i++) dst[t + 128*i] = src[t + 128*i];
    __syncthreads();

    int c = t & 63, r0 = t >> 6;
    float acc[16];
    float bc = bo[c];
    #pragma unroll
    for (int i = 0; i < 16; i++) acc[i] = bc;
    #pragma unroll 4
    for (int k = 0; k < 64; k += 4) {
        float w0 = __ldg(Wo + (k+0)*64 + c);
        float w1 = __ldg(Wo + (k+1)*64 + c);
        float w2 = __ldg(Wo + (k+2)*64 + c);
        float w3 = __ldg(Wo + (k+3)*64 + c);
        #pragma unroll
        for (int i = 0; i < 16; i++) {
            float4 f = *(const float4*)&fat[(r0 + 2*i)*64 + k];
            acc[i] += f.x*w0 + f.y*w1 + f.z*w2 + f.w*w3;
        }
    }
    #pragma unroll
    for (int i = 0; i < 16; i++) out[(rbase + r0 + 2*i)*64 + c] = acc[i];
}

// ---------------- launch ----------------------------------------------------
extern "C" void kernel_launch(void* const* d_in, const int* in_sizes, int n_in,
                              void* d_out, int out_size) {
    const float* desc   = (const float*)d_in[0];
    const float* feat   = (const float*)d_in[1];
    const int*   coords = (const int*)  d_in[2];
    const float* pose   = (const float*)d_in[3];
    const float* Wq = (const float*)d_in[4];  const float* bq = (const float*)d_in[5];
    const float* Wk = (const float*)d_in[6];  const float* bk = (const float*)d_in[7];
    const float* Wv = (const float*)d_in[8];  const float* bv = (const float*)d_in[9];
    const float* Wp = (const float*)d_in[10]; const float* bp = (const float*)d_in[11];
    const float* Wo = (const float*)d_in[12]; const float* bo = (const float*)d_in[13];
    float* out = (float*)d_out;

    int smem_bytes = CHCHUNK * CHSTR * sizeof(float);   // 166,528 B
    cudaFuncSetAttribute(stripe_gather_kernel,
                         cudaFuncAttributeMaxDynamicSharedMemorySize, smem_bytes);

    zero_pose_kernel<<<BB + 1, 64>>>(pose, Wp, bp);
    bin_kernel<<<(BB*NN)/256, 256>>>(coords);
    stripe_gather_kernel<<<dim3(DD/CHCHUNK, NSTRIPE, BB), 256, smem_bytes>>>(feat, coords);
    projection_kernel<<<512, 256>>>(desc, Wq, bq, Wk, bk, Wv, bv);
    attn_mma_kernel<<<dim3(8, NHH, BB), 256>>>();
    outproj_kernel<<<(BB*NN)/32, 128>>>(Wo, bo, out);
}

// round 8
// speedup vs baseline: 1.5666x; 1.5666x over previous
#include <cuda_runtime.h>
#include <cstdint>

#define BB 16
#define NN 1024
#define DD 64
#define NHH 4
#define HDD 16
#define HH 256
#define WW 256

// ---------------- scratch (device globals: no runtime allocation) ----------
__device__ float g_Q[BB*NHH*NN*HDD];          // (b,h,n,j) 4MB
__device__ float g_K[BB*NHH*NN*HDD];          // 4MB
__device__ float g_V[BB*NHH*NN*HDD];          // 4MB
__device__ float g_PF[BB*NN*DD];              // patch means 4MB
__device__ float g_att[BB*NN*DD];             // pose-scaled attention out 4MB
__device__ float g_pose[BB*DD];               // 1 + pose_mod

// ---------------- helpers ---------------------------------------------------
__device__ __forceinline__ float ex2f(float x) {
    float y;
    asm("ex2.approx.f32 %0, %1;" : "=f"(y) : "f"(x));
    return y;
}
__device__ __forceinline__ uint32_t tf32cvt(float f) {
    uint32_t u;
    asm("cvt.rna.tf32.f32 %0, %1;" : "=r"(u) : "f"(f));
    return u;
}
__device__ __forceinline__ void mma_tf32(float& d0, float& d1, float& d2, float& d3,
                                         uint32_t a0, uint32_t a1, uint32_t a2, uint32_t a3,
                                         uint32_t b0, uint32_t b1) {
    asm("mma.sync.aligned.m16n8k8.row.col.f32.tf32.tf32.f32 "
        "{%0,%1,%2,%3}, {%4,%5,%6,%7}, {%8,%9}, {%0,%1,%2,%3};"
        : "+f"(d0), "+f"(d1), "+f"(d2), "+f"(d3)
        : "r"(a0), "r"(a1), "r"(a2), "r"(a3), "r"(b0), "r"(b1));
}

// ---------------- K1: patch-mean gather (paired-lane coalesced) -------------
// Blocks [0,1024): warp = 2 points; lane = (ch-pair, half). One LDG.128
// covers 16 planes x 2 contiguous float4 halves. shfl_xor(1) recombines.
// Blocks [1024,1040): pose tail.
__global__ __launch_bounds__(256) void gather_kernel(
    const float* __restrict__ feat, const int* __restrict__ coords,
    const float* __restrict__ pe, const float* __restrict__ Wp,
    const float* __restrict__ bp)
{
    if (blockIdx.x >= 1024) {           // ---- pose tail blocks ----
        int b = blockIdx.x - 1024;
        int d = threadIdx.x;
        if (d < 64) {
            float s = bp[d];
            #pragma unroll 8
            for (int p = 0; p < 64; p++) s += pe[b*64 + p] * Wp[p*64 + d];
            g_pose[b*64 + d] = 1.0f + s;
        }
        return;
    }

    int t = threadIdx.x, w = t >> 5, lane = t & 31;
    int ch2 = lane >> 1, half = lane & 1;

    #pragma unroll
    for (int ip = 0; ip < 2; ip++) {
        int gp = blockIdx.x*16 + w*2 + ip;
        int b  = gp >> 10;
        int y = __ldg(coords + gp*2 + 0);    // warp-uniform
        int x = __ldg(coords + gp*2 + 1);
        int s = x - 2;
        bool fast = (s >= 0) && (s <= 248);

        float part[4] = {0.f, 0.f, 0.f, 0.f};

        if (fast) {
            int a = s & ~3;
            int o = s - a;                   // 0..3 warp-uniform
            #pragma unroll
            for (int dy = 0; dy < 5; dy++) {
                int yy = y + dy - 2;
                int yc = min(max(yy, 0), HH-1);
                float m = (yy == yc) ? 1.0f : 0.0f;
                #pragma unroll
                for (int cp = 0; cp < 4; cp++) {
                    int ch = cp*16 + ch2;
                    const float4* p = (const float4*)
                        (feat + ((size_t)(b*64 + ch) << 16) + yc*WW + a) + half;
                    float4 v = __ldg(p);
                    float ps;
                    if (half == 0) {
                        ps = v.w;
                        if (o < 3) ps += v.z;
                        if (o < 2) ps += v.y;
                        if (o < 1) ps += v.x;
                    } else {
                        ps = v.x;
                        if (o > 0) ps += v.y;
                        if (o > 1) ps += v.z;
                        if (o > 2) ps += v.w;
                    }
                    part[cp] = fmaf(m, ps, part[cp]);
                }
            }
        } else {
            int base = x - 2 + half*4;
            int cnt  = half ? 1 : 4;
            for (int dy = 0; dy < 5; dy++) {
                int yy = y + dy - 2;
                if (yy < 0 || yy >= HH) continue;
                #pragma unroll
                for (int cp = 0; cp < 4; cp++) {
                    int ch = cp*16 + ch2;
                    const float* row = feat + ((size_t)(b*64 + ch) << 16) + yy*WW;
                    float ps = 0.f;
                    #pragma unroll
                    for (int i = 0; i < 4; i++) {
                        if (i < cnt) {
                            int xx = base + i;
                            if (xx >= 0 && xx < WW) ps += __ldg(row + xx);
                        }
                    }
                    part[cp] += ps;
                }
            }
        }

        #pragma unroll
        for (int cp = 0; cp < 4; cp++) {
            float tot = part[cp] + __shfl_xor_sync(0xffffffff, part[cp], 1);
            if (half == 0)
                g_PF[(size_t)gp*64 + cp*16 + ch2] = tot * 0.04f;
        }
    }
}

// ---------------- K2: Q/K/V projection (float4 k-chunks) --------------------
__global__ __launch_bounds__(256) void projection_kernel(
    const float* __restrict__ desc,
    const float* __restrict__ Wq, const float* __restrict__ bq,
    const float* __restrict__ Wk, const float* __restrict__ bk,
    const float* __restrict__ Wv, const float* __restrict__ bv)
{
    __shared__ float pf[32*64];
    __shared__ float dsc[32*64];

    int t = threadIdx.x;
    int gp0 = blockIdx.x * 32;
    int b   = gp0 >> 10;
    int n0  = gp0 & 1023;

    const float4* dsrc = (const float4*)(desc + (size_t)gp0*64);
    const float4* psrc = (const float4*)(g_PF + (size_t)gp0*64);
    ((float4*)dsc)[t]       = dsrc[t];
    ((float4*)dsc)[t + 256] = dsrc[t + 256];
    ((float4*)pf)[t]        = psrc[t];
    ((float4*)pf)[t + 256]  = psrc[t + 256];
    __syncthreads();

    int c = t & 63;
    int pbase = t >> 6;
    float accq[8], acck[8], accv[8];
    float bqc = bq[c], bkc = bk[c], bvc = bv[c];
    #pragma unroll
    for (int i = 0; i < 8; i++) { accq[i]=bqc; acck[i]=bkc; accv[i]=bvc; }

    #pragma unroll 4
    for (int kc = 0; kc < 16; kc++) {
        int k = kc*4;
        float q0 = __ldg(Wq + (k+0)*64 + c), q1 = __ldg(Wq + (k+1)*64 + c);
        float q2 = __ldg(Wq + (k+2)*64 + c), q3 = __ldg(Wq + (k+3)*64 + c);
        float k0 = __ldg(Wk + (k+0)*64 + c), k1 = __ldg(Wk + (k+1)*64 + c);
        float k2 = __ldg(Wk + (k+2)*64 + c), k3 = __ldg(Wk + (k+3)*64 + c);
        float v0 = __ldg(Wv + (k+0)*64 + c), v1 = __ldg(Wv + (k+1)*64 + c);
        float v2 = __ldg(Wv + (k+2)*64 + c), v3 = __ldg(Wv + (k+3)*64 + c);
        #pragma unroll
        for (int i = 0; i < 8; i++) {
            int p = pbase + 4*i;
            float4 d4 = *(const float4*)&dsc[p*64 + k];
            float4 f4 = *(const float4*)&pf[p*64 + k];
            accq[i] += d4.x*q0 + d4.y*q1 + d4.z*q2 + d4.w*q3;
            acck[i] += f4.x*k0 + f4.y*k1 + f4.z*k2 + f4.w*k3;
            accv[i] += f4.x*v0 + f4.y*v1 + f4.z*v2 + f4.w*v3;
        }
    }

    int h = c >> 4, j = c & 15;
    size_t base = (size_t)(b*NHH + h) * NN;
    #pragma unroll
    for (int i = 0; i < 8; i++) {
        int p = pbase + 4*i;
        size_t idx = (base + n0 + p) * HDD + j;
        g_Q[idx] = accq[i];
        g_K[idx] = acck[i];
        g_V[idx] = accv[i];
    }
}

// ---------------- K3: all-tf32 tensor-core attention ------------------------
#define KPAD 20
#define VPAD 24
__global__ __launch_bounds__(256) void attn_mma_kernel() {
    __shared__ uint32_t Ks[64*KPAD];     // tf32 bits, [key][d] padded
    __shared__ uint32_t Vs[64*VPAD];     // tf32 bits, [perm key][d] padded

    int t = threadIdx.x;
    int w = t >> 5, lane = t & 31, g = lane >> 2, t4 = lane & 3;
    int b = blockIdx.z, h = blockIdx.y;
    size_t bh = (size_t)(b*NHH + h) * NN * HDD;
    const float* Kg = g_K + bh;
    const float* Vg = g_V + bh;

    int qrow = blockIdx.x*128 + w*16;
    const float* Qp = g_Q + bh + (size_t)qrow*HDD;
    const float CSC = 0.25f * 1.4426950408889634f;

    uint32_t qa[2][4];
    #pragma unroll
    for (int c = 0; c < 2; c++) {
        qa[c][0] = tf32cvt(Qp[ g   *16 + c*8 + t4    ] * CSC);
        qa[c][1] = tf32cvt(Qp[(g+8)*16 + c*8 + t4    ] * CSC);
        qa[c][2] = tf32cvt(Qp[ g   *16 + c*8 + t4 + 4] * CSC);
        qa[c][3] = tf32cvt(Qp[(g+8)*16 + c*8 + t4 + 4] * CSC);
    }

    float o0[4] = {0,0,0,0};
    float o1[4] = {0,0,0,0};
    float rs0 = 0.0f, rs1 = 0.0f;

    int key = t >> 2, dc = t & 3;
    int vrow = (key & ~7) + 4*(key & 1) + ((key & 7) >> 1);

    float4 kreg = ((const float4*)Kg)[t];
    float4 vreg = ((const float4*)Vg)[t];

    for (int tile = 0; tile < 16; tile++) {
        __syncthreads();
        {
            uint32_t* kd = Ks + key*KPAD + dc*4;
            kd[0] = tf32cvt(kreg.x); kd[1] = tf32cvt(kreg.y);
            kd[2] = tf32cvt(kreg.z); kd[3] = tf32cvt(kreg.w);
            uint4 vv;
            vv.x = tf32cvt(vreg.x); vv.y = tf32cvt(vreg.y);
            vv.z = tf32cvt(vreg.z); vv.w = tf32cvt(vreg.w);
            *(uint4*)(Vs + vrow*VPAD + dc*4) = vv;
        }
        __syncthreads();
        if (tile < 15) {
            kreg = ((const float4*)(Kg + (size_t)(tile+1)*64*16))[t];
            vreg = ((const float4*)(Vg + (size_t)(tile+1)*64*16))[t];
        }

        #pragma unroll
        for (int j = 0; j < 8; j++) {
            float d0=0.f, d1=0.f, d2=0.f, d3=0.f;
            #pragma unroll
            for (int c = 0; c < 2; c++) {
                const uint32_t* kb = Ks + (j*8+g)*KPAD + c*8 + t4;
                mma_tf32(d0,d1,d2,d3, qa[c][0],qa[c][1],qa[c][2],qa[c][3],
                         kb[0], kb[4]);
            }
            float p0 = ex2f(d0), p1 = ex2f(d1), p2 = ex2f(d2), p3 = ex2f(d3);
            rs0 += p0 + p1;
            rs1 += p2 + p3;
            uint32_t a0 = tf32cvt(p0), a1 = tf32cvt(p2);
            uint32_t a2 = tf32cvt(p1), a3 = tf32cvt(p3);
            uint32_t b00 = Vs[(j*8 + t4    )*VPAD + g    ];
            uint32_t b01 = Vs[(j*8 + t4 + 4)*VPAD + g    ];
            uint32_t b10 = Vs[(j*8 + t4    )*VPAD + g + 8];
            uint32_t b11 = Vs[(j*8 + t4 + 4)*VPAD + g + 8];
            mma_tf32(o0[0],o0[1],o0[2],o0[3], a0,a1,a2,a3, b00,b01);
            mma_tf32(o1[0],o1[1],o1[2],o1[3], a0,a1,a2,a3, b10,b11);
        }
    }

    rs0 += __shfl_xor_sync(0xffffffff, rs0, 1);
    rs0 += __shfl_xor_sync(0xffffffff, rs0, 2);
    rs1 += __shfl_xor_sync(0xffffffff, rs1, 1);
    rs1 += __shfl_xor_sync(0xffffffff, rs1, 2);
    float inv0 = 1.0f / rs0;
    float inv1 = 1.0f / rs1;

    const float* ps = g_pose + b*64 + h*16;
    size_t r0 = ((size_t)b*NN + qrow + g    )*64 + h*16;
    size_t r1 = ((size_t)b*NN + qrow + g + 8)*64 + h*16;
    #pragma unroll
    for (int nd = 0; nd < 2; nd++) {
        const float* o = nd ? o1 : o0;
        int cc = nd*8 + 2*t4;
        float p0 = ps[cc], p1 = ps[cc+1];
        *(float2*)&g_att[r0 + cc] = make_float2(o[0]*inv0*p0, o[1]*inv0*p1);
        *(float2*)&g_att[r1 + cc] = make_float2(o[2]*inv1*p0, o[3]*inv1*p1);
    }
}

// ---------------- K4: out = g_att @ Wo + bo (32 rows/block) -----------------
__global__ __launch_bounds__(128) void outproj_kernel(const float* __restrict__ Wo,
                                                      const float* __restrict__ bo,
                                                      float* __restrict__ out) {
    __shared__ float fat[32*64];
    int t = threadIdx.x;
    size_t rbase = (size_t)blockIdx.x * 32;
    const float4* src = (const float4*)(g_att + rbase*64);
    float4* dst = (float4*)fat;
    #pragma unroll
    for (int i = 0; i < 4; i++) dst[t + 128*i] = src[t + 128*i];
    __syncthreads();

    int c = t & 63, r0 = t >> 6;
    float acc[16];
    float bc = bo[c];
    #pragma unroll
    for (int i = 0; i < 16; i++) acc[i] = bc;
    #pragma unroll 4
    for (int k = 0; k < 64; k += 4) {
        float w0 = __ldg(Wo + (k+0)*64 + c);
        float w1 = __ldg(Wo + (k+1)*64 + c);
        float w2 = __ldg(Wo + (k+2)*64 + c);
        float w3 = __ldg(Wo + (k+3)*64 + c);
        #pragma unroll
        for (int i = 0; i < 16; i++) {
            float4 f = *(const float4*)&fat[(r0 + 2*i)*64 + k];
            acc[i] += f.x*w0 + f.y*w1 + f.z*w2 + f.w*w3;
        }
    }
    #pragma unroll
    for (int i = 0; i < 16; i++) out[(rbase + r0 + 2*i)*64 + c] = acc[i];
}

// ---------------- launch ----------------------------------------------------
extern "C" void kernel_launch(void* const* d_in, const int* in_sizes, int n_in,
                              void* d_out, int out_size) {
    const float* desc   = (const float*)d_in[0];
    const float* feat   = (const float*)d_in[1];
    const int*   coords = (const int*)  d_in[2];
    const float* pose   = (const float*)d_in[3];
    const float* Wq = (const float*)d_in[4];  const float* bq = (const float*)d_in[5];
    const float* Wk = (const float*)d_in[6];  const float* bk = (const float*)d_in[7];
    const float* Wv = (const float*)d_in[8];  const float* bv = (const float*)d_in[9];
    const float* Wp = (const float*)d_in[10]; const float* bp = (const float*)d_in[11];
    const float* Wo = (const float*)d_in[12]; const float* bo = (const float*)d_in[13];
    float* out = (float*)d_out;

    gather_kernel<<<1024 + BB, 256>>>(feat, coords, pose, Wp, bp);
    projection_kernel<<<512, 256>>>(desc, Wq, bq, Wk, bk, Wv, bv);
    attn_mma_kernel<<<dim3(8, NHH, BB), 256>>>();
    outproj_kernel<<<(BB*NN)/32, 128>>>(Wo, bo, out);
}

// round 9
// speedup vs baseline: 1.7014x; 1.0860x over previous
#include <cuda_runtime.h>
#include <cstdint>

#define BB 16
#define NN 1024
#define DD 64
#define NHH 4
#define HDD 16
#define HH 256
#define WW 256

// ---------------- scratch (device globals: no runtime allocation) ----------
__device__ float g_Q[BB*NHH*NN*HDD];          // (b,h,n,j) 4MB
__device__ float g_K[BB*NHH*NN*HDD];          // 4MB
__device__ float g_V[BB*NHH*NN*HDD];          // 4MB
__device__ float g_PF[BB*NN*DD];              // patch means 4MB
__device__ float g_att[BB*NN*DD];             // pose-scaled attention out 4MB
__device__ float g_pose[BB*DD];               // 1 + pose_mod

// ---------------- helpers ---------------------------------------------------
__device__ __forceinline__ float ex2f(float x) {
    float y;
    asm("ex2.approx.f32 %0, %1;" : "=f"(y) : "f"(x));
    return y;
}
__device__ __forceinline__ uint32_t tf32cvt(float f) {
    uint32_t u;
    asm("cvt.rna.tf32.f32 %0, %1;" : "=r"(u) : "f"(f));
    return u;
}
__device__ __forceinline__ void mma_tf32(float& d0, float& d1, float& d2, float& d3,
                                         uint32_t a0, uint32_t a1, uint32_t a2, uint32_t a3,
                                         uint32_t b0, uint32_t b1) {
    asm("mma.sync.aligned.m16n8k8.row.col.f32.tf32.tf32.f32 "
        "{%0,%1,%2,%3}, {%4,%5,%6,%7}, {%8,%9}, {%0,%1,%2,%3};"
        : "+f"(d0), "+f"(d1), "+f"(d2), "+f"(d3)
        : "r"(a0), "r"(a1), "r"(a2), "r"(a3), "r"(b0), "r"(b1));
}

// ---------------- K1: patch-mean gather (paired-lane coalesced) -------------
__global__ __launch_bounds__(256) void gather_kernel(
    const float* __restrict__ feat, const int* __restrict__ coords,
    const float* __restrict__ pe, const float* __restrict__ Wp,
    const float* __restrict__ bp)
{
    if (blockIdx.x >= 1024) {           // ---- pose tail blocks ----
        int b = blockIdx.x - 1024;
        int d = threadIdx.x;
        if (d < 64) {
            float s = bp[d];
            #pragma unroll 8
            for (int p = 0; p < 64; p++) s += pe[b*64 + p] * Wp[p*64 + d];
            g_pose[b*64 + d] = 1.0f + s;
        }
        return;
    }

    int t = threadIdx.x, w = t >> 5, lane = t & 31;
    int ch2 = lane >> 1, half = lane & 1;

    #pragma unroll
    for (int ip = 0; ip < 2; ip++) {
        int gp = blockIdx.x*16 + w*2 + ip;
        int b  = gp >> 10;
        int y = __ldg(coords + gp*2 + 0);    // warp-uniform
        int x = __ldg(coords + gp*2 + 1);
        int s = x - 2;
        bool fast = (s >= 0) && (s <= 248);

        float part[4] = {0.f, 0.f, 0.f, 0.f};

        if (fast) {
            int a = s & ~3;
            int o = s - a;
            #pragma unroll
            for (int dy = 0; dy < 5; dy++) {
                int yy = y + dy - 2;
                int yc = min(max(yy, 0), HH-1);
                float m = (yy == yc) ? 1.0f : 0.0f;
                #pragma unroll
                for (int cp = 0; cp < 4; cp++) {
                    int ch = cp*16 + ch2;
                    const float4* p = (const float4*)
                        (feat + ((size_t)(b*64 + ch) << 16) + yc*WW + a) + half;
                    float4 v = __ldg(p);
                    float ps;
                    if (half == 0) {
                        ps = v.w;
                        if (o < 3) ps += v.z;
                        if (o < 2) ps += v.y;
                        if (o < 1) ps += v.x;
                    } else {
                        ps = v.x;
                        if (o > 0) ps += v.y;
                        if (o > 1) ps += v.z;
                        if (o > 2) ps += v.w;
                    }
                    part[cp] = fmaf(m, ps, part[cp]);
                }
            }
        } else {
            int base = x - 2 + half*4;
            int cnt  = half ? 1 : 4;
            for (int dy = 0; dy < 5; dy++) {
                int yy = y + dy - 2;
                if (yy < 0 || yy >= HH) continue;
                #pragma unroll
                for (int cp = 0; cp < 4; cp++) {
                    int ch = cp*16 + ch2;
                    const float* row = feat + ((size_t)(b*64 + ch) << 16) + yy*WW;
                    float ps = 0.f;
                    #pragma unroll
                    for (int i = 0; i < 4; i++) {
                        if (i < cnt) {
                            int xx = base + i;
                            if (xx >= 0 && xx < WW) ps += __ldg(row + xx);
                        }
                    }
                    part[cp] += ps;
                }
            }
        }

        #pragma unroll
        for (int cp = 0; cp < 4; cp++) {
            float tot = part[cp] + __shfl_xor_sync(0xffffffff, part[cp], 1);
            if (half == 0)
                g_PF[(size_t)gp*64 + cp*16 + ch2] = tot * 0.04f;
        }
    }
}

// ---------------- K2: Q/K/V projection via tf32 mma -------------------------
// CTA = 128 points, 8 warps (warp = 16 rows). Pass 1: Q = desc@Wq + bq.
// Pass 2: [K|V] = pf@[Wk|Wv] + [bk|bv]. A pad stride 68, B pad stride 136
// (both conflict-free for the m16n8k8 fragment access patterns).
#define ASTR 68
#define BSTR 136
extern __shared__ uint32_t PS[];
__global__ __launch_bounds__(256) void projection_mma_kernel(
    const float* __restrict__ desc,
    const float* __restrict__ Wq, const float* __restrict__ bq,
    const float* __restrict__ Wk, const float* __restrict__ bk,
    const float* __restrict__ Wv, const float* __restrict__ bv)
{
    uint32_t* As = PS;                  // 128 x ASTR
    uint32_t* Bs = PS + 128*ASTR;       // 64 x BSTR

    int t = threadIdx.x;
    int w = t >> 5, lane = t & 31, g = lane >> 2, t4 = lane & 3;
    int gp0 = blockIdx.x * 128;
    int b = gp0 >> 10, n0 = gp0 & 1023;

    // ======== pass 1: Q ========
    #pragma unroll
    for (int it = 0; it < 8; it++) {        // A = desc tile (128x64)
        int i = t + 256*it;
        int r = i >> 4, c4 = (i & 15)*4;
        float4 v = __ldg((const float4*)(desc + (size_t)(gp0 + r)*64 + c4));
        *(uint4*)&As[r*ASTR + c4] =
            make_uint4(tf32cvt(v.x), tf32cvt(v.y), tf32cvt(v.z), tf32cvt(v.w));
    }
    #pragma unroll
    for (int it = 0; it < 4; it++) {        // B = Wq (64x64)
        int i = t + 256*it;
        int k = i >> 4, n4 = (i & 15)*4;
        float4 v = __ldg((const float4*)(Wq + k*64 + n4));
        *(uint4*)&Bs[k*BSTR + n4] =
            make_uint4(tf32cvt(v.x), tf32cvt(v.y), tf32cvt(v.z), tf32cvt(v.w));
    }
    __syncthreads();

    {
        uint32_t a[8][4];
        #pragma unroll
        for (int kc = 0; kc < 8; kc++) {
            int r0 = (w*16 + g)*ASTR + kc*8 + t4;
            a[kc][0] = As[r0];           a[kc][1] = As[r0 + 8*ASTR];
            a[kc][2] = As[r0 + 4];       a[kc][3] = As[r0 + 8*ASTR + 4];
        }
        #pragma unroll
        for (int nch = 0; nch < 8; nch++) {
            float d0=0.f, d1=0.f, d2=0.f, d3=0.f;
            #pragma unroll
            for (int kc = 0; kc < 8; kc++)
                mma_tf32(d0,d1,d2,d3, a[kc][0],a[kc][1],a[kc][2],a[kc][3],
                         Bs[(kc*8 + t4)*BSTR + nch*8 + g],
                         Bs[(kc*8 + t4 + 4)*BSTR + nch*8 + g]);
            int c = nch*8 + 2*t4;
            float bb0 = __ldg(bq + c), bb1 = __ldg(bq + c + 1);
            int h = c >> 4, j = c & 15;
            size_t idx = ((size_t)(b*NHH + h)*NN + n0 + w*16 + g)*HDD + j;
            *(float2*)&g_Q[idx]          = make_float2(d0 + bb0, d1 + bb1);
            *(float2*)&g_Q[idx + 8*HDD]  = make_float2(d2 + bb0, d3 + bb1);
        }
    }
    __syncthreads();

    // ======== pass 2: K | V ========
    #pragma unroll
    for (int it = 0; it < 8; it++) {        // A = pf tile (128x64)
        int i = t + 256*it;
        int r = i >> 4, c4 = (i & 15)*4;
        float4 v = *(const float4*)(g_PF + (size_t)(gp0 + r)*64 + c4);
        *(uint4*)&As[r*ASTR + c4] =
            make_uint4(tf32cvt(v.x), tf32cvt(v.y), tf32cvt(v.z), tf32cvt(v.w));
    }
    #pragma unroll
    for (int it = 0; it < 4; it++) {        // B cols 0..63 = Wk
        int i = t + 256*it;
        int k = i >> 4, n4 = (i & 15)*4;
        float4 v = __ldg((const float4*)(Wk + k*64 + n4));
        *(uint4*)&Bs[k*BSTR + n4] =
            make_uint4(tf32cvt(v.x), tf32cvt(v.y), tf32cvt(v.z), tf32cvt(v.w));
    }
    #pragma unroll
    for (int it = 0; it < 4; it++) {        // B cols 64..127 = Wv
        int i = t + 256*it;
        int k = i >> 4, n4 = (i & 15)*4;
        float4 v = __ldg((const float4*)(Wv + k*64 + n4));
        *(uint4*)&Bs[k*BSTR + 64 + n4] =
            make_uint4(tf32cvt(v.x), tf32cvt(v.y), tf32cvt(v.z), tf32cvt(v.w));
    }
    __syncthreads();

    {
        uint32_t a[8][4];
        #pragma unroll
        for (int kc = 0; kc < 8; kc++) {
            int r0 = (w*16 + g)*ASTR + kc*8 + t4;
            a[kc][0] = As[r0];           a[kc][1] = As[r0 + 8*ASTR];
            a[kc][2] = As[r0 + 4];       a[kc][3] = As[r0 + 8*ASTR + 4];
        }
        #pragma unroll
        for (int nch = 0; nch < 16; nch++) {
            float d0=0.f, d1=0.f, d2=0.f, d3=0.f;
            #pragma unroll
            for (int kc = 0; kc < 8; kc++)
                mma_tf32(d0,d1,d2,d3, a[kc][0],a[kc][1],a[kc][2],a[kc][3],
                         Bs[(kc*8 + t4)*BSTR + nch*8 + g],
                         Bs[(kc*8 + t4 + 4)*BSTR + nch*8 + g]);
            int cfull = nch*8 + 2*t4;
            bool isK = (cfull < 64);
            int c = isK ? cfull : (cfull - 64);
            const float* bias = isK ? bk : bv;
            float* dst = isK ? g_K : g_V;
            float bb0 = __ldg(bias + c), bb1 = __ldg(bias + c + 1);
            int h = c >> 4, j = c & 15;
            size_t idx = ((size_t)(b*NHH + h)*NN + n0 + w*16 + g)*HDD + j;
            *(float2*)&dst[idx]         = make_float2(d0 + bb0, d1 + bb1);
            *(float2*)&dst[idx + 8*HDD] = make_float2(d2 + bb0, d3 + bb1);
        }
    }
}

// ---------------- K3: all-tf32 tensor-core attention ------------------------
#define KPAD 20
#define VPAD 24
__global__ __launch_bounds__(256) void attn_mma_kernel() {
    __shared__ uint32_t Ks[64*KPAD];
    __shared__ uint32_t Vs[64*VPAD];

    int t = threadIdx.x;
    int w = t >> 5, lane = t & 31, g = lane >> 2, t4 = lane & 3;
    int b = blockIdx.z, h = blockIdx.y;
    size_t bh = (size_t)(b*NHH + h) * NN * HDD;
    const float* Kg = g_K + bh;
    const float* Vg = g_V + bh;

    int qrow = blockIdx.x*128 + w*16;
    const float* Qp = g_Q + bh + (size_t)qrow*HDD;
    const float CSC = 0.25f * 1.4426950408889634f;

    uint32_t qa[2][4];
    #pragma unroll
    for (int c = 0; c < 2; c++) {
        qa[c][0] = tf32cvt(Qp[ g   *16 + c*8 + t4    ] * CSC);
        qa[c][1] = tf32cvt(Qp[(g+8)*16 + c*8 + t4    ] * CSC);
        qa[c][2] = tf32cvt(Qp[ g   *16 + c*8 + t4 + 4] * CSC);
        qa[c][3] = tf32cvt(Qp[(g+8)*16 + c*8 + t4 + 4] * CSC);
    }

    float o0[4] = {0,0,0,0};
    float o1[4] = {0,0,0,0};
    float rs0 = 0.0f, rs1 = 0.0f;

    int key = t >> 2, dc = t & 3;
    int vrow = (key & ~7) + 4*(key & 1) + ((key & 7) >> 1);

    float4 kreg = ((const float4*)Kg)[t];
    float4 vreg = ((const float4*)Vg)[t];

    for (int tile = 0; tile < 16; tile++) {
        __syncthreads();
        {
            uint32_t* kd = Ks + key*KPAD + dc*4;
            kd[0] = tf32cvt(kreg.x); kd[1] = tf32cvt(kreg.y);
            kd[2] = tf32cvt(kreg.z); kd[3] = tf32cvt(kreg.w);
            uint4 vv;
            vv.x = tf32cvt(vreg.x); vv.y = tf32cvt(vreg.y);
            vv.z = tf32cvt(vreg.z); vv.w = tf32cvt(vreg.w);
            *(uint4*)(Vs + vrow*VPAD + dc*4) = vv;
        }
        __syncthreads();
        if (tile < 15) {
            kreg = ((const float4*)(Kg + (size_t)(tile+1)*64*16))[t];
            vreg = ((const float4*)(Vg + (size_t)(tile+1)*64*16))[t];
        }

        #pragma unroll
        for (int j = 0; j < 8; j++) {
            float d0=0.f, d1=0.f, d2=0.f, d3=0.f;
            #pragma unroll
            for (int c = 0; c < 2; c++) {
                const uint32_t* kb = Ks + (j*8+g)*KPAD + c*8 + t4;
                mma_tf32(d0,d1,d2,d3, qa[c][0],qa[c][1],qa[c][2],qa[c][3],
                         kb[0], kb[4]);
            }
            float p0 = ex2f(d0), p1 = ex2f(d1), p2 = ex2f(d2), p3 = ex2f(d3);
            rs0 += p0 + p1;
            rs1 += p2 + p3;
            uint32_t a0 = tf32cvt(p0), a1 = tf32cvt(p2);
            uint32_t a2 = tf32cvt(p1), a3 = tf32cvt(p3);
            uint32_t b00 = Vs[(j*8 + t4    )*VPAD + g    ];
            uint32_t b01 = Vs[(j*8 + t4 + 4)*VPAD + g    ];
            uint32_t b10 = Vs[(j*8 + t4    )*VPAD + g + 8];
            uint32_t b11 = Vs[(j*8 + t4 + 4)*VPAD + g + 8];
            mma_tf32(o0[0],o0[1],o0[2],o0[3], a0,a1,a2,a3, b00,b01);
            mma_tf32(o1[0],o1[1],o1[2],o1[3], a0,a1,a2,a3, b10,b11);
        }
    }

    rs0 += __shfl_xor_sync(0xffffffff, rs0, 1);
    rs0 += __shfl_xor_sync(0xffffffff, rs0, 2);
    rs1 += __shfl_xor_sync(0xffffffff, rs1, 1);
    rs1 += __shfl_xor_sync(0xffffffff, rs1, 2);
    float inv0 = 1.0f / rs0;
    float inv1 = 1.0f / rs1;

    const float* ps = g_pose + b*64 + h*16;
    size_t r0 = ((size_t)b*NN + qrow + g    )*64 + h*16;
    size_t r1 = ((size_t)b*NN + qrow + g + 8)*64 + h*16;
    #pragma unroll
    for (int nd = 0; nd < 2; nd++) {
        const float* o = nd ? o1 : o0;
        int cc = nd*8 + 2*t4;
        float p0 = ps[cc], p1 = ps[cc+1];
        *(float2*)&g_att[r0 + cc] = make_float2(o[0]*inv0*p0, o[1]*inv0*p1);
        *(float2*)&g_att[r1 + cc] = make_float2(o[2]*inv1*p0, o[3]*inv1*p1);
    }
}

// ---------------- K4: out = g_att @ Wo + bo (32 rows/block) -----------------
__global__ __launch_bounds__(128) void outproj_kernel(const float* __restrict__ Wo,
                                                      const float* __restrict__ bo,
                                                      float* __restrict__ out) {
    __shared__ float fat[32*64];
    int t = threadIdx.x;
    size_t rbase = (size_t)blockIdx.x * 32;
    const float4* src = (const float4*)(g_att + rbase*64);
    float4* dst = (float4*)fat;
    #pragma unroll
    for (int i = 0; i < 4; i++) dst[t + 128*i] = src[t + 128*i];
    __syncthreads();

    int c = t & 63, r0 = t >> 6;
    float acc[16];
    float bc = bo[c];
    #pragma unroll
    for (int i = 0; i < 16; i++) acc[i] = bc;
    #pragma unroll 4
    for (int k = 0; k < 64; k += 4) {
        float w0 = __ldg(Wo + (k+0)*64 + c);
        float w1 = __ldg(Wo + (k+1)*64 + c);
        float w2 = __ldg(Wo + (k+2)*64 + c);
        float w3 = __ldg(Wo + (k+3)*64 + c);
        #pragma unroll
        for (int i = 0; i < 16; i++) {
            float4 f = *(const float4*)&fat[(r0 + 2*i)*64 + k];
            acc[i] += f.x*w0 + f.y*w1 + f.z*w2 + f.w*w3;
        }
    }
    #pragma unroll
    for (int i = 0; i < 16; i++) out[(rbase + r0 + 2*i)*64 + c] = acc[i];
}

// ---------------- launch ----------------------------------------------------
extern "C" void kernel_launch(void* const* d_in, const int* in_sizes, int n_in,
                              void* d_out, int out_size) {
    const float* desc   = (const float*)d_in[0];
    const float* feat   = (const float*)d_in[1];
    const int*   coords = (const int*)  d_in[2];
    const float* pose   = (const float*)d_in[3];
    const float* Wq = (const float*)d_in[4];  const float* bq = (const float*)d_in[5];
    const float* Wk = (const float*)d_in[6];  const float* bk = (const float*)d_in[7];
    const float* Wv = (const float*)d_in[8];  const float* bv = (const float*)d_in[9];
    const float* Wp = (const float*)d_in[10]; const float* bp = (const float*)d_in[11];
    const float* Wo = (const float*)d_in[12]; const float* bo = (const float*)d_in[13];
    float* out = (float*)d_out;

    int psm = (128*ASTR + 64*BSTR) * 4;     // 69,632 B
    cudaFuncSetAttribute(projection_mma_kernel,
                         cudaFuncAttributeMaxDynamicSharedMemorySize, psm);

    gather_kernel<<<1024 + BB, 256>>>(feat, coords, pose, Wp, bp);
    projection_mma_kernel<<<128, 256, psm>>>(desc, Wq, bq, Wk, bk, Wv, bv);
    attn_mma_kernel<<<dim3(8, NHH, BB), 256>>>();
    outproj_kernel<<<(BB*NN)/32, 128>>>(Wo, bo, out);
}

// round 10
// speedup vs baseline: 1.8312x; 1.0763x over previous
#include <cuda_runtime.h>
#include <cstdint>

#define BB 16
#define NN 1024
#define DD 64
#define NHH 4
#define HDD 16
#define HH 256
#define WW 256

// ---------------- scratch (device globals: no runtime allocation) ----------
__device__ float g_Q[BB*NHH*NN*HDD];          // (b,h,n,j) 4MB
__device__ float g_K[BB*NHH*NN*HDD];          // 4MB
__device__ float g_V[BB*NHH*NN*HDD];          // 4MB
__device__ float g_PF[BB*NN*DD];              // patch means 4MB
__device__ float g_att[BB*NN*DD];             // pose-scaled attention out 4MB
__device__ float g_pose[BB*DD];               // 1 + pose_mod

// ---------------- helpers ---------------------------------------------------
__device__ __forceinline__ float ex2f(float x) {
    float y;
    asm("ex2.approx.f32 %0, %1;" : "=f"(y) : "f"(x));
    return y;
}
__device__ __forceinline__ uint32_t tf32cvt(float f) {
    uint32_t u;
    asm("cvt.rna.tf32.f32 %0, %1;" : "=r"(u) : "f"(f));
    return u;
}
__device__ __forceinline__ void mma_tf32(float& d0, float& d1, float& d2, float& d3,
                                         uint32_t a0, uint32_t a1, uint32_t a2, uint32_t a3,
                                         uint32_t b0, uint32_t b1) {
    asm("mma.sync.aligned.m16n8k8.row.col.f32.tf32.tf32.f32 "
        "{%0,%1,%2,%3}, {%4,%5,%6,%7}, {%8,%9}, {%0,%1,%2,%3};"
        : "+f"(d0), "+f"(d1), "+f"(d2), "+f"(d3)
        : "r"(a0), "r"(a1), "r"(a2), "r"(a3), "r"(b0), "r"(b1));
}

// ---------------- K1: patch-mean gather (paired-lane coalesced) -------------
__global__ __launch_bounds__(256) void gather_kernel(
    const float* __restrict__ feat, const int* __restrict__ coords,
    const float* __restrict__ pe, const float* __restrict__ Wp,
    const float* __restrict__ bp)
{
    if (blockIdx.x >= 1024) {           // ---- pose tail blocks ----
        int b = blockIdx.x - 1024;
        int d = threadIdx.x;
        if (d < 64) {
            float s = bp[d];
            #pragma unroll 8
            for (int p = 0; p < 64; p++) s += pe[b*64 + p] * Wp[p*64 + d];
            g_pose[b*64 + d] = 1.0f + s;
        }
        return;
    }

    int t = threadIdx.x, w = t >> 5, lane = t & 31;
    int ch2 = lane >> 1, half = lane & 1;

    #pragma unroll
    for (int ip = 0; ip < 2; ip++) {
        int gp = blockIdx.x*16 + w*2 + ip;
        int b  = gp >> 10;
        int y = __ldg(coords + gp*2 + 0);    // warp-uniform
        int x = __ldg(coords + gp*2 + 1);
        int s = x - 2;
        bool fast = (s >= 0) && (s <= 248);

        float part[4] = {0.f, 0.f, 0.f, 0.f};

        if (fast) {
            int a = s & ~3;
            int o = s - a;
            #pragma unroll
            for (int dy = 0; dy < 5; dy++) {
                int yy = y + dy - 2;
                int yc = min(max(yy, 0), HH-1);
                float m = (yy == yc) ? 1.0f : 0.0f;
                #pragma unroll
                for (int cp = 0; cp < 4; cp++) {
                    int ch = cp*16 + ch2;
                    const float4* p = (const float4*)
                        (feat + ((size_t)(b*64 + ch) << 16) + yc*WW + a) + half;
                    float4 v = __ldg(p);
                    float ps;
                    if (half == 0) {
                        ps = v.w;
                        if (o < 3) ps += v.z;
                        if (o < 2) ps += v.y;
                        if (o < 1) ps += v.x;
                    } else {
                        ps = v.x;
                        if (o > 0) ps += v.y;
                        if (o > 1) ps += v.z;
                        if (o > 2) ps += v.w;
                    }
                    part[cp] = fmaf(m, ps, part[cp]);
                }
            }
        } else {
            int base = x - 2 + half*4;
            int cnt  = half ? 1 : 4;
            for (int dy = 0; dy < 5; dy++) {
                int yy = y + dy - 2;
                if (yy < 0 || yy >= HH) continue;
                #pragma unroll
                for (int cp = 0; cp < 4; cp++) {
                    int ch = cp*16 + ch2;
                    const float* row = feat + ((size_t)(b*64 + ch) << 16) + yy*WW;
                    float ps = 0.f;
                    #pragma unroll
                    for (int i = 0; i < 4; i++) {
                        if (i < cnt) {
                            int xx = base + i;
                            if (xx >= 0 && xx < WW) ps += __ldg(row + xx);
                        }
                    }
                    part[cp] += ps;
                }
            }
        }

        #pragma unroll
        for (int cp = 0; cp < 4; cp++) {
            float tot = part[cp] + __shfl_xor_sync(0xffffffff, part[cp], 1);
            if (half == 0)
                g_PF[(size_t)gp*64 + cp*16 + ch2] = tot * 0.04f;
        }
    }
}

// ---------------- K2: Q/K/V projection via tf32 mma -------------------------
#define ASTR 68
#define BSTR 136
extern __shared__ uint32_t PS[];
__global__ __launch_bounds__(256) void projection_mma_kernel(
    const float* __restrict__ desc,
    const float* __restrict__ Wq, const float* __restrict__ bq,
    const float* __restrict__ Wk, const float* __restrict__ bk,
    const float* __restrict__ Wv, const float* __restrict__ bv)
{
    uint32_t* As = PS;                  // 128 x ASTR
    uint32_t* Bs = PS + 128*ASTR;       // 64 x BSTR

    int t = threadIdx.x;
    int w = t >> 5, lane = t & 31, g = lane >> 2, t4 = lane & 3;
    int gp0 = blockIdx.x * 128;
    int b = gp0 >> 10, n0 = gp0 & 1023;

    // ======== pass 1: Q ========
    #pragma unroll
    for (int it = 0; it < 8; it++) {
        int i = t + 256*it;
        int r = i >> 4, c4 = (i & 15)*4;
        float4 v = __ldg((const float4*)(desc + (size_t)(gp0 + r)*64 + c4));
        *(uint4*)&As[r*ASTR + c4] =
            make_uint4(tf32cvt(v.x), tf32cvt(v.y), tf32cvt(v.z), tf32cvt(v.w));
    }
    #pragma unroll
    for (int it = 0; it < 4; it++) {
        int i = t + 256*it;
        int k = i >> 4, n4 = (i & 15)*4;
        float4 v = __ldg((const float4*)(Wq + k*64 + n4));
        *(uint4*)&Bs[k*BSTR + n4] =
            make_uint4(tf32cvt(v.x), tf32cvt(v.y), tf32cvt(v.z), tf32cvt(v.w));
    }
    __syncthreads();

    {
        uint32_t a[8][4];
        #pragma unroll
        for (int kc = 0; kc < 8; kc++) {
            int r0 = (w*16 + g)*ASTR + kc*8 + t4;
            a[kc][0] = As[r0];           a[kc][1] = As[r0 + 8*ASTR];
            a[kc][2] = As[r0 + 4];       a[kc][3] = As[r0 + 8*ASTR + 4];
        }
        #pragma unroll
        for (int nch = 0; nch < 8; nch++) {
            float d0=0.f, d1=0.f, d2=0.f, d3=0.f;
            #pragma unroll
            for (int kc = 0; kc < 8; kc++)
                mma_tf32(d0,d1,d2,d3, a[kc][0],a[kc][1],a[kc][2],a[kc][3],
                         Bs[(kc*8 + t4)*BSTR + nch*8 + g],
                         Bs[(kc*8 + t4 + 4)*BSTR + nch*8 + g]);
            int c = nch*8 + 2*t4;
            float bb0 = __ldg(bq + c), bb1 = __ldg(bq + c + 1);
            int h = c >> 4, j = c & 15;
            size_t idx = ((size_t)(b*NHH + h)*NN + n0 + w*16 + g)*HDD + j;
            *(float2*)&g_Q[idx]          = make_float2(d0 + bb0, d1 + bb1);
            *(float2*)&g_Q[idx + 8*HDD]  = make_float2(d2 + bb0, d3 + bb1);
        }
    }
    __syncthreads();

    // ======== pass 2: K | V ========
    #pragma unroll
    for (int it = 0; it < 8; it++) {
        int i = t + 256*it;
        int r = i >> 4, c4 = (i & 15)*4;
        float4 v = *(const float4*)(g_PF + (size_t)(gp0 + r)*64 + c4);
        *(uint4*)&As[r*ASTR + c4] =
            make_uint4(tf32cvt(v.x), tf32cvt(v.y), tf32cvt(v.z), tf32cvt(v.w));
    }
    #pragma unroll
    for (int it = 0; it < 4; it++) {
        int i = t + 256*it;
        int k = i >> 4, n4 = (i & 15)*4;
        float4 v = __ldg((const float4*)(Wk + k*64 + n4));
        *(uint4*)&Bs[k*BSTR + n4] =
            make_uint4(tf32cvt(v.x), tf32cvt(v.y), tf32cvt(v.z), tf32cvt(v.w));
    }
    #pragma unroll
    for (int it = 0; it < 4; it++) {
        int i = t + 256*it;
        int k = i >> 4, n4 = (i & 15)*4;
        float4 v = __ldg((const float4*)(Wv + k*64 + n4));
        *(uint4*)&Bs[k*BSTR + 64 + n4] =
            make_uint4(tf32cvt(v.x), tf32cvt(v.y), tf32cvt(v.z), tf32cvt(v.w));
    }
    __syncthreads();

    {
        uint32_t a[8][4];
        #pragma unroll
        for (int kc = 0; kc < 8; kc++) {
            int r0 = (w*16 + g)*ASTR + kc*8 + t4;
            a[kc][0] = As[r0];           a[kc][1] = As[r0 + 8*ASTR];
            a[kc][2] = As[r0 + 4];       a[kc][3] = As[r0 + 8*ASTR + 4];
        }
        #pragma unroll
        for (int nch = 0; nch < 16; nch++) {
            float d0=0.f, d1=0.f, d2=0.f, d3=0.f;
            #pragma unroll
            for (int kc = 0; kc < 8; kc++)
                mma_tf32(d0,d1,d2,d3, a[kc][0],a[kc][1],a[kc][2],a[kc][3],
                         Bs[(kc*8 + t4)*BSTR + nch*8 + g],
                         Bs[(kc*8 + t4 + 4)*BSTR + nch*8 + g]);
            int cfull = nch*8 + 2*t4;
            bool isK = (cfull < 64);
            int c = isK ? cfull : (cfull - 64);
            const float* bias = isK ? bk : bv;
            float* dst = isK ? g_K : g_V;
            float bb0 = __ldg(bias + c), bb1 = __ldg(bias + c + 1);
            int h = c >> 4, j = c & 15;
            size_t idx = ((size_t)(b*NHH + h)*NN + n0 + w*16 + g)*HDD + j;
            *(float2*)&dst[idx]         = make_float2(d0 + bb0, d1 + bb1);
            *(float2*)&dst[idx + 8*HDD] = make_float2(d2 + bb0, d3 + bb1);
        }
    }
}

// ---------------- K3: all-tf32 tensor-core attention ------------------------
#define KPAD 20
#define VPAD 24
__global__ __launch_bounds__(256) void attn_mma_kernel() {
    __shared__ uint32_t Ks[64*KPAD];
    __shared__ uint32_t Vs[64*VPAD];

    int t = threadIdx.x;
    int w = t >> 5, lane = t & 31, g = lane >> 2, t4 = lane & 3;
    int b = blockIdx.z, h = blockIdx.y;
    size_t bh = (size_t)(b*NHH + h) * NN * HDD;
    const float* Kg = g_K + bh;
    const float* Vg = g_V + bh;

    int qrow = blockIdx.x*128 + w*16;
    const float* Qp = g_Q + bh + (size_t)qrow*HDD;
    const float CSC = 0.25f * 1.4426950408889634f;

    uint32_t qa[2][4];
    #pragma unroll
    for (int c = 0; c < 2; c++) {
        qa[c][0] = tf32cvt(Qp[ g   *16 + c*8 + t4    ] * CSC);
        qa[c][1] = tf32cvt(Qp[(g+8)*16 + c*8 + t4    ] * CSC);
        qa[c][2] = tf32cvt(Qp[ g   *16 + c*8 + t4 + 4] * CSC);
        qa[c][3] = tf32cvt(Qp[(g+8)*16 + c*8 + t4 + 4] * CSC);
    }

    float o0[4] = {0,0,0,0};
    float o1[4] = {0,0,0,0};
    float rs0 = 0.0f, rs1 = 0.0f;

    int key = t >> 2, dc = t & 3;
    int vrow = (key & ~7) + 4*(key & 1) + ((key & 7) >> 1);

    float4 kreg = ((const float4*)Kg)[t];
    float4 vreg = ((const float4*)Vg)[t];

    for (int tile = 0; tile < 16; tile++) {
        __syncthreads();
        {
            uint32_t* kd = Ks + key*KPAD + dc*4;
            kd[0] = tf32cvt(kreg.x); kd[1] = tf32cvt(kreg.y);
            kd[2] = tf32cvt(kreg.z); kd[3] = tf32cvt(kreg.w);
            uint4 vv;
            vv.x = tf32cvt(vreg.x); vv.y = tf32cvt(vreg.y);
            vv.z = tf32cvt(vreg.z); vv.w = tf32cvt(vreg.w);
            *(uint4*)(Vs + vrow*VPAD + dc*4) = vv;
        }
        __syncthreads();
        if (tile < 15) {
            kreg = ((const float4*)(Kg + (size_t)(tile+1)*64*16))[t];
            vreg = ((const float4*)(Vg + (size_t)(tile+1)*64*16))[t];
        }

        #pragma unroll
        for (int j = 0; j < 8; j++) {
            float d0=0.f, d1=0.f, d2=0.f, d3=0.f;
            #pragma unroll
            for (int c = 0; c < 2; c++) {
                const uint32_t* kb = Ks + (j*8+g)*KPAD + c*8 + t4;
                mma_tf32(d0,d1,d2,d3, qa[c][0],qa[c][1],qa[c][2],qa[c][3],
                         kb[0], kb[4]);
            }
            float p0 = ex2f(d0), p1 = ex2f(d1), p2 = ex2f(d2), p3 = ex2f(d3);
            rs0 += p0 + p1;
            rs1 += p2 + p3;
            // raw f32 bits as tf32 (HW reads top 19 bits; truncation bias
            // cancels between numerator and denominator of softmax)
            uint32_t a0 = __float_as_uint(p0), a1 = __float_as_uint(p2);
            uint32_t a2 = __float_as_uint(p1), a3 = __float_as_uint(p3);
            uint32_t b00 = Vs[(j*8 + t4    )*VPAD + g    ];
            uint32_t b01 = Vs[(j*8 + t4 + 4)*VPAD + g    ];
            uint32_t b10 = Vs[(j*8 + t4    )*VPAD + g + 8];
            uint32_t b11 = Vs[(j*8 + t4 + 4)*VPAD + g + 8];
            mma_tf32(o0[0],o0[1],o0[2],o0[3], a0,a1,a2,a3, b00,b01);
            mma_tf32(o1[0],o1[1],o1[2],o1[3], a0,a1,a2,a3, b10,b11);
        }
    }

    rs0 += __shfl_xor_sync(0xffffffff, rs0, 1);
    rs0 += __shfl_xor_sync(0xffffffff, rs0, 2);
    rs1 += __shfl_xor_sync(0xffffffff, rs1, 1);
    rs1 += __shfl_xor_sync(0xffffffff, rs1, 2);
    float inv0 = 1.0f / rs0;
    float inv1 = 1.0f / rs1;

    const float* ps = g_pose + b*64 + h*16;
    size_t r0 = ((size_t)b*NN + qrow + g    )*64 + h*16;
    size_t r1 = ((size_t)b*NN + qrow + g + 8)*64 + h*16;
    #pragma unroll
    for (int nd = 0; nd < 2; nd++) {
        const float* o = nd ? o1 : o0;
        int cc = nd*8 + 2*t4;
        float p0 = ps[cc], p1 = ps[cc+1];
        *(float2*)&g_att[r0 + cc] = make_float2(o[0]*inv0*p0, o[1]*inv0*p1);
        *(float2*)&g_att[r1 + cc] = make_float2(o[2]*inv1*p0, o[3]*inv1*p1);
    }
}

// ---------------- K4: out = g_att @ Wo + bo via tf32 mma --------------------
#define OBSTR 72
extern __shared__ uint32_t OS[];
__global__ __launch_bounds__(256) void outproj_mma_kernel(
    const float* __restrict__ Wo, const float* __restrict__ bo,
    float* __restrict__ out)
{
    uint32_t* As = OS;                  // 128 x ASTR
    uint32_t* Bs = OS + 128*ASTR;       // 64 x OBSTR

    int t = threadIdx.x;
    int w = t >> 5, lane = t & 31, g = lane >> 2, t4 = lane & 3;
    size_t gp0 = (size_t)blockIdx.x * 128;

    #pragma unroll
    for (int it = 0; it < 8; it++) {        // A = g_att tile (128x64)
        int i = t + 256*it;
        int r = i >> 4, c4 = (i & 15)*4;
        float4 v = *(const float4*)(g_att + (gp0 + r)*64 + c4);
        *(uint4*)&As[r*ASTR + c4] =
            make_uint4(tf32cvt(v.x), tf32cvt(v.y), tf32cvt(v.z), tf32cvt(v.w));
    }
    #pragma unroll
    for (int it = 0; it < 4; it++) {        // B = Wo (64x64)
        int i = t + 256*it;
        int k = i >> 4, n4 = (i & 15)*4;
        float4 v = __ldg((const float4*)(Wo + k*64 + n4));
        *(uint4*)&Bs[k*OBSTR + n4] =
            make_uint4(tf32cvt(v.x), tf32cvt(v.y), tf32cvt(v.z), tf32cvt(v.w));
    }
    __syncthreads();

    uint32_t a[8][4];
    #pragma unroll
    for (int kc = 0; kc < 8; kc++) {
        int r0 = (w*16 + g)*ASTR + kc*8 + t4;
        a[kc][0] = As[r0];           a[kc][1] = As[r0 + 8*ASTR];
        a[kc][2] = As[r0 + 4];       a[kc][3] = As[r0 + 8*ASTR + 4];
    }
    #pragma unroll
    for (int nch = 0; nch < 8; nch++) {
        float d0=0.f, d1=0.f, d2=0.f, d3=0.f;
        #pragma unroll
        for (int kc = 0; kc < 8; kc++)
            mma_tf32(d0,d1,d2,d3, a[kc][0],a[kc][1],a[kc][2],a[kc][3],
                     Bs[(kc*8 + t4)*OBSTR + nch*8 + g],
                     Bs[(kc*8 + t4 + 4)*OBSTR + nch*8 + g]);
        int c = nch*8 + 2*t4;
        float bb0 = __ldg(bo + c), bb1 = __ldg(bo + c + 1);
        size_t r0i = (gp0 + w*16 + g)*64 + c;
        *(float2*)&out[r0i]          = make_float2(d0 + bb0, d1 + bb1);
        *(float2*)&out[r0i + 8*64]   = make_float2(d2 + bb0, d3 + bb1);
    }
}

// ---------------- launch ----------------------------------------------------
extern "C" void kernel_launch(void* const* d_in, const int* in_sizes, int n_in,
                              void* d_out, int out_size) {
    const float* desc   = (const float*)d_in[0];
    const float* feat   = (const float*)d_in[1];
    const int*   coords = (const int*)  d_in[2];
    const float* pose   = (const float*)d_in[3];
    const float* Wq = (const float*)d_in[4];  const float* bq = (const float*)d_in[5];
    const float* Wk = (const float*)d_in[6];  const float* bk = (const float*)d_in[7];
    const float* Wv = (const float*)d_in[8];  const float* bv = (const float*)d_in[9];
    const float* Wp = (const float*)d_in[10]; const float* bp = (const float*)d_in[11];
    const float* Wo = (const float*)d_in[12]; const float* bo = (const float*)d_in[13];
    float* out = (float*)d_out;

    int psm = (128*ASTR + 64*BSTR) * 4;     // 69,632 B
    cudaFuncSetAttribute(projection_mma_kernel,
                         cudaFuncAttributeMaxDynamicSharedMemorySize, psm);
    int osm = (128*ASTR + 64*OBSTR) * 4;    // 53,248 B
    cudaFuncSetAttribute(outproj_mma_kernel,
                         cudaFuncAttributeMaxDynamicSharedMemorySize, osm);

    gather_kernel<<<1024 + BB, 256>>>(feat, coords, pose, Wp, bp);
    projection_mma_kernel<<<128, 256, psm>>>(desc, Wq, bq, Wk, bk, Wv, bv);
    attn_mma_kernel<<<dim3(8, NHH, BB), 256>>>();
    outproj_mma_kernel<<<128, 256, osm>>>(Wo, bo, out);
}